// round 1
// baseline (speedup 1.0000x reference)
#include <cuda_runtime.h>
#include <math_constants.h>

#define N_BINS 15

// Global scratch (no allocation allowed): per-bin count / sum(conf) / sum(acc)
__device__ float g_cnt[N_BINS];
__device__ float g_conf[N_BINS];
__device__ float g_acc[N_BINS];

__global__ void mce_init_kernel() {
    int i = threadIdx.x;
    if (i < N_BINS) {
        g_cnt[i]  = 0.0f;
        g_conf[i] = 0.0f;
        g_acc[i]  = 0.0f;
    }
}

// One warp per row. Row = 128 fp32 = 32 float4 -> one float4 per lane,
// fully coalesced 512B per warp per row.
__global__ void __launch_bounds__(256) mce_main_kernel(
    const float4* __restrict__ logits4,   // [nrows * 32] float4
    const int*    __restrict__ labels,    // [nrows]
    int nrows)
{
    __shared__ float s_cnt[N_BINS];
    __shared__ float s_conf[N_BINS];
    __shared__ float s_acc[N_BINS];

    int tid = threadIdx.x;
    if (tid < N_BINS) {
        s_cnt[tid]  = 0.0f;
        s_conf[tid] = 0.0f;
        s_acc[tid]  = 0.0f;
    }
    __syncthreads();

    int lane   = tid & 31;
    int warp   = (blockIdx.x * blockDim.x + tid) >> 5;
    int nwarps = (gridDim.x * blockDim.x) >> 5;

    for (int row = warp; row < nrows; row += nwarps) {
        float4 v = logits4[(size_t)row * 32 + lane];

        // local max + argmax (global column index), first-index tiebreak
        float m  = v.x;
        int   mi = lane * 4;
        if (v.y > m) { m = v.y; mi = lane * 4 + 1; }
        if (v.z > m) { m = v.z; mi = lane * 4 + 2; }
        if (v.w > m) { m = v.w; mi = lane * 4 + 3; }

        // warp butterfly max with lowest-index tiebreak (commutative, all
        // lanes converge to the same (m, mi))
        #pragma unroll
        for (int off = 16; off; off >>= 1) {
            float om = __shfl_xor_sync(0xffffffffu, m,  off);
            int   oi = __shfl_xor_sync(0xffffffffu, mi, off);
            if (om > m || (om == m && oi < mi)) { m = om; mi = oi; }
        }

        // sum of exp(x - max); max element contributes exactly 1
        float s = __expf(v.x - m) + __expf(v.y - m)
                + __expf(v.z - m) + __expf(v.w - m);
        #pragma unroll
        for (int off = 16; off; off >>= 1)
            s += __shfl_xor_sync(0xffffffffu, s, off);

        if (lane == 0) {
            float conf = 1.0f / s;                 // = exp(max)/sum exp
            // bin i covers (i/15, (i+1)/15]  ->  ceil(conf*15)-1, clipped
            int bin = (int)ceilf(conf * (float)N_BINS) - 1;
            bin = min(max(bin, 0), N_BINS - 1);
            float acc = (mi == labels[row]) ? 1.0f : 0.0f;
            atomicAdd(&s_cnt[bin],  1.0f);
            atomicAdd(&s_conf[bin], conf);
            atomicAdd(&s_acc[bin],  acc);
        }
    }

    __syncthreads();
    if (tid < N_BINS) {
        float c = s_cnt[tid];
        if (c != 0.0f) {
            atomicAdd(&g_cnt[tid],  c);
            atomicAdd(&g_conf[tid], s_conf[tid]);
            atomicAdd(&g_acc[tid],  s_acc[tid]);
        }
    }
}

__global__ void mce_final_kernel(float* __restrict__ out) {
    if (threadIdx.x == 0) {
        float mce = -CUDART_INF_F;
        #pragma unroll
        for (int i = 0; i < N_BINS; i++) {
            float c    = g_cnt[i];
            float prob = 0.0f, accu = 0.0f;
            if (c > 0.0f) {
                prob = g_conf[i] / c;
                accu = g_acc[i] / c;
                float gap = fabsf(prob - accu);
                if (gap > mce) mce = gap;
            }
            out[1 + i]          = prob;   // avg confidence per bin
            out[1 + N_BINS + i] = accu;   // accuracy per bin
        }
        out[0] = mce;
    }
}

extern "C" void kernel_launch(void* const* d_in, const int* in_sizes, int n_in,
                              void* d_out, int out_size) {
    const float4* logits = (const float4*)d_in[0];
    const int*    labels = (const int*)d_in[1];
    int nrows = in_sizes[1];               // labels element count == N rows

    mce_init_kernel<<<1, 32>>>();
    // persistent-style grid: ~8 blocks/SM x 148 SMs; grid-stride over rows
    mce_main_kernel<<<1184, 256>>>(logits, labels, nrows);
    mce_final_kernel<<<1, 32>>>((float*)d_out);
}

// round 2
// speedup vs baseline: 1.2811x; 1.2811x over previous
#include <cuda_runtime.h>
#include <math_constants.h>

#define N_BINS 15
#define RPI 4          // rows per warp per iteration (MLP batching)

// Global scratch (no allocation allowed): per-bin count / sum(conf) / sum(acc)
__device__ float g_cnt[N_BINS];
__device__ float g_conf[N_BINS];
__device__ float g_acc[N_BINS];

__global__ void mce_init_kernel() {
    int i = threadIdx.x;
    if (i < N_BINS) {
        g_cnt[i]  = 0.0f;
        g_conf[i] = 0.0f;
        g_acc[i]  = 0.0f;
    }
}

// One warp per row, 4 rows batched per iteration. Row = 128 fp32 = 32 float4,
// one float4 per lane; 4 consecutive rows -> 2KB contiguous streaming per warp.
__global__ void __launch_bounds__(256) mce_main_kernel(
    const float4* __restrict__ logits4,   // [nrows * 32] float4
    const int*    __restrict__ labels,    // [nrows]
    int nrows)
{
    __shared__ float s_cnt[N_BINS];
    __shared__ float s_conf[N_BINS];
    __shared__ float s_acc[N_BINS];

    int tid = threadIdx.x;
    if (tid < N_BINS) {
        s_cnt[tid]  = 0.0f;
        s_conf[tid] = 0.0f;
        s_acc[tid]  = 0.0f;
    }
    __syncthreads();

    int lane   = tid & 31;
    int warp   = (blockIdx.x * blockDim.x + tid) >> 5;
    int nwarps = (gridDim.x * blockDim.x) >> 5;

    for (int base = warp * RPI; base < nrows; base += nwarps * RPI) {
        int nr = min(RPI, nrows - base);

        // ---- front-batched loads: 4 independent LDG.128 (MLP_p1 = 4) ----
        float4 v[RPI];
        int    lab[RPI];
        #pragma unroll
        for (int r = 0; r < RPI; r++) {
            if (r < nr) {
                v[r]   = __ldcs(&logits4[(size_t)(base + r) * 32 + lane]);
                lab[r] = labels[base + r];          // uniform across warp -> broadcast
            } else {
                v[r] = make_float4(0.f, 0.f, 0.f, 0.f);
                lab[r] = -1;
            }
        }

        // ---- per-lane max of 4 ----
        float m[RPI];
        #pragma unroll
        for (int r = 0; r < RPI; r++)
            m[r] = fmaxf(fmaxf(v[r].x, v[r].y), fmaxf(v[r].z, v[r].w));

        // ---- interleaved warp max butterflies (4 independent chains) ----
        #pragma unroll
        for (int off = 16; off; off >>= 1) {
            #pragma unroll
            for (int r = 0; r < RPI; r++)
                m[r] = fmaxf(m[r], __shfl_xor_sync(0xffffffffu, m[r], off));
        }

        // ---- sum of exp(x - max), interleaved butterflies ----
        float s[RPI];
        #pragma unroll
        for (int r = 0; r < RPI; r++)
            s[r] = __expf(v[r].x - m[r]) + __expf(v[r].y - m[r])
                 + __expf(v[r].z - m[r]) + __expf(v[r].w - m[r]);
        #pragma unroll
        for (int off = 16; off; off >>= 1) {
            #pragma unroll
            for (int r = 0; r < RPI; r++)
                s[r] += __shfl_xor_sync(0xffffffffu, s[r], off);
        }

        // ---- epilogue per row: acc via ballot, bin, shared atomics ----
        #pragma unroll
        for (int r = 0; r < RPI; r++) {
            int l = lab[r];
            // lane that owns the label column checks equality with the row max
            bool mine = ((l >> 2) == lane);
            int  sub  = l & 3;
            float lv  = (sub == 0) ? v[r].x : (sub == 1) ? v[r].y
                      : (sub == 2) ? v[r].z : v[r].w;
            bool ok = mine && (lv == m[r]);
            unsigned b = __ballot_sync(0xffffffffu, ok);

            if (lane == 0 && r < nr) {
                float conf = 1.0f / s[r];           // = exp(max)/sum exp
                // bin i covers (i/15, (i+1)/15]  ->  ceil(conf*15)-1, clipped
                int bin = (int)ceilf(conf * (float)N_BINS) - 1;
                bin = min(max(bin, 0), N_BINS - 1);
                float acc = (b != 0u) ? 1.0f : 0.0f;
                atomicAdd(&s_cnt[bin],  1.0f);
                atomicAdd(&s_conf[bin], conf);
                atomicAdd(&s_acc[bin],  acc);
            }
        }
    }

    __syncthreads();
    if (tid < N_BINS) {
        float c = s_cnt[tid];
        if (c != 0.0f) {
            atomicAdd(&g_cnt[tid],  c);
            atomicAdd(&g_conf[tid], s_conf[tid]);
            atomicAdd(&g_acc[tid],  s_acc[tid]);
        }
    }
}

__global__ void mce_final_kernel(float* __restrict__ out) {
    if (threadIdx.x == 0) {
        float mce = -CUDART_INF_F;
        #pragma unroll
        for (int i = 0; i < N_BINS; i++) {
            float c    = g_cnt[i];
            float prob = 0.0f, accu = 0.0f;
            if (c > 0.0f) {
                prob = g_conf[i] / c;
                accu = g_acc[i] / c;
                float gap = fabsf(prob - accu);
                if (gap > mce) mce = gap;
            }
            out[1 + i]          = prob;   // avg confidence per bin
            out[1 + N_BINS + i] = accu;   // accuracy per bin
        }
        out[0] = mce;
    }
}

extern "C" void kernel_launch(void* const* d_in, const int* in_sizes, int n_in,
                              void* d_out, int out_size) {
    const float4* logits = (const float4*)d_in[0];
    const int*    labels = (const int*)d_in[1];
    int nrows = in_sizes[1];               // labels element count == N rows

    mce_init_kernel<<<1, 32>>>();
    // 8 blocks/SM x 148 SMs, grid-stride over row groups of 4
    mce_main_kernel<<<1184, 256>>>(logits, labels, nrows);
    mce_final_kernel<<<1, 32>>>((float*)d_out);
}

// round 4
// speedup vs baseline: 1.6230x; 1.2669x over previous
#include <cuda_runtime.h>
#include <math_constants.h>

#define N_BINS 15
#define RPI 8          // rows per warp per iteration (MLP batching)

// Global scratch (no allocation allowed): per-bin count / sum(conf) / sum(acc).
// Zeroed at module load; mce_final_kernel re-zeroes after each use, so every
// graph replay starts from zero.
__device__ float g_cnt[N_BINS];
__device__ float g_conf[N_BINS];
__device__ float g_acc[N_BINS];

__device__ __forceinline__ float ex2f(float x) {
    float r;
    asm volatile("ex2.approx.f32 %0, %1;" : "=f"(r) : "f"(x));
    return r;
}

#define LOG2E 1.4426950408889634f

// One warp per row, 8 rows batched per iteration. Row = 128 fp32 = 32 float4,
// one float4 per lane; 8 consecutive rows -> 4KB contiguous per warp-iter.
// No atomics in the main loop: lane b (b<15) owns register accumulators for
// bin b; results are flushed through shared -> global once at kernel end.
__global__ void __launch_bounds__(256) mce_main_kernel(
    const float4* __restrict__ logits4,   // [nrows * 32] float4
    const int*    __restrict__ labels,    // [nrows]
    int nrows)
{
    __shared__ float s_cnt[N_BINS];
    __shared__ float s_conf[N_BINS];
    __shared__ float s_acc[N_BINS];

    int tid = threadIdx.x;
    if (tid < N_BINS) {
        s_cnt[tid]  = 0.0f;
        s_conf[tid] = 0.0f;
        s_acc[tid]  = 0.0f;
    }
    __syncthreads();

    int lane   = tid & 31;
    int warp   = (blockIdx.x * blockDim.x + tid) >> 5;
    int nwarps = (gridDim.x * blockDim.x) >> 5;

    // per-lane register accumulators: lane b accumulates bin b (b < 15)
    float r_cnt = 0.0f, r_conf = 0.0f, r_acc = 0.0f;

    for (int base = warp * RPI; base < nrows; base += nwarps * RPI) {
        int nr = min(RPI, nrows - base);

        // ---- front-batched loads: 8 independent LDG.128 (MLP_p1 = 8) ----
        float4 v[RPI];
        int    lab[RPI];
        #pragma unroll
        for (int r = 0; r < RPI; r++) {
            int row = base + ((r < nr) ? r : 0);        // clamp (dup row of group)
            v[r]   = __ldcs(&logits4[(size_t)row * 32 + lane]);
            lab[r] = labels[row];                       // uniform -> broadcast
        }

        // ---- per-lane max of 4, then interleaved warp max butterflies ----
        float m[RPI];
        #pragma unroll
        for (int r = 0; r < RPI; r++)
            m[r] = fmaxf(fmaxf(v[r].x, v[r].y), fmaxf(v[r].z, v[r].w));
        #pragma unroll
        for (int off = 16; off; off >>= 1) {
            #pragma unroll
            for (int r = 0; r < RPI; r++)
                m[r] = fmaxf(m[r], __shfl_xor_sync(0xffffffffu, m[r], off));
        }

        // ---- sum of exp(x-m) = ex2(x*log2e - m*log2e), interleaved ----
        float s[RPI];
        #pragma unroll
        for (int r = 0; r < RPI; r++) {
            float mL = m[r] * LOG2E;
            float e0 = ex2f(fmaf(v[r].x, LOG2E, -mL));
            float e1 = ex2f(fmaf(v[r].y, LOG2E, -mL));
            float e2 = ex2f(fmaf(v[r].z, LOG2E, -mL));
            float e3 = ex2f(fmaf(v[r].w, LOG2E, -mL));
            s[r] = (e0 + e1) + (e2 + e3);
        }
        #pragma unroll
        for (int off = 16; off; off >>= 1) {
            #pragma unroll
            for (int r = 0; r < RPI; r++)
                s[r] += __shfl_xor_sync(0xffffffffu, s[r], off);
        }

        // ---- epilogue: every lane knows m,s -> bin/conf; acc via ballot ----
        #pragma unroll
        for (int r = 0; r < RPI; r++) {
            int l = lab[r];
            bool mine = ((l >> 2) == lane);
            int  sub  = l & 3;
            float lv  = (sub == 0) ? v[r].x : (sub == 1) ? v[r].y
                      : (sub == 2) ? v[r].z : v[r].w;
            unsigned b = __ballot_sync(0xffffffffu, mine && (lv == m[r]));

            float conf = 1.0f / s[r];            // = exp(max)/sum exp
            // bin i covers (i/15, (i+1)/15] -> ceil(conf*15)-1, clipped
            int bin = (int)ceilf(conf * (float)N_BINS) - 1;
            bin = min(max(bin, 0), N_BINS - 1);

            // register histogram: lane 'bin' takes it (lanes >=15 never match)
            if (bin == lane && r < nr) {
                r_cnt  += 1.0f;
                r_conf += conf;
                r_acc  += (b != 0u) ? 1.0f : 0.0f;
            }
        }
    }

    // ---- flush: per-warp registers -> shared -> global (once) ----
    if (lane < N_BINS && r_cnt != 0.0f) {
        atomicAdd(&s_cnt[lane],  r_cnt);
        atomicAdd(&s_conf[lane], r_conf);
        atomicAdd(&s_acc[lane],  r_acc);
    }
    __syncthreads();
    if (tid < N_BINS) {
        float c = s_cnt[tid];
        if (c != 0.0f) {
            atomicAdd(&g_cnt[tid],  c);
            atomicAdd(&g_conf[tid], s_conf[tid]);
            atomicAdd(&g_acc[tid],  s_acc[tid]);
        }
    }
}

__global__ void mce_final_kernel(float* __restrict__ out) {
    if (threadIdx.x == 0) {
        float mce = -CUDART_INF_F;
        #pragma unroll
        for (int i = 0; i < N_BINS; i++) {
            float c    = g_cnt[i];
            float prob = 0.0f, accu = 0.0f;
            if (c > 0.0f) {
                prob = g_conf[i] / c;
                accu = g_acc[i] / c;
                float gap = fabsf(prob - accu);
                if (gap > mce) mce = gap;
            }
            out[1 + i]          = prob;
            out[1 + N_BINS + i] = accu;
            // reset for the next graph replay
            g_cnt[i] = 0.0f; g_conf[i] = 0.0f; g_acc[i] = 0.0f;
        }
        out[0] = mce;
    }
}

extern "C" void kernel_launch(void* const* d_in, const int* in_sizes, int n_in,
                              void* d_out, int out_size) {
    const float4* logits = (const float4*)d_in[0];
    const int*    labels = (const int*)d_in[1];
    int nrows = in_sizes[1];               // labels element count == N rows

    mce_main_kernel<<<888, 256>>>(logits, labels, nrows);
    mce_final_kernel<<<1, 32>>>((float*)d_out);
}

// round 5
// speedup vs baseline: 2.1497x; 1.3245x over previous
#include <cuda_runtime.h>
#include <math_constants.h>

#define N_BINS 15
#define RPW 8          // rows per warp per iter (one row per 4-lane segment)

// Global scratch (no allocation allowed). Zeroed at module load; the fused
// finalizer re-zeroes after each use, so every graph replay starts from zero.
__device__ float    g_cnt[N_BINS];
__device__ float    g_conf[N_BINS];
__device__ float    g_acc[N_BINS];
__device__ unsigned g_done;

__device__ __forceinline__ float ex2f(float x) {
    float r;
    asm volatile("ex2.approx.f32 %0, %1;" : "=f"(r) : "f"(x));
    return r;
}

#define LOG2E 1.4426950408889634f

// 4 lanes per row: lane covers 32 floats (8 float4, stride-4 within the row).
// A warp processes 8 consecutive rows per iteration (4 KB contiguous).
// Reduction = 2 butterfly levels (xor 1, xor 2) across the 4-lane segment —
// one SHFL instruction reduces all 8 rows at once.
// No atomics in the hot loop: lane b (<15) owns register accumulators for bin b.
__global__ void __launch_bounds__(256) mce_main_kernel(
    const float4* __restrict__ logits4,   // [nrows * 32] float4
    const float*  __restrict__ logits,    // same buffer, scalar view
    const int*    __restrict__ labels,    // [nrows]
    float*        __restrict__ out,
    int nrows)
{
    __shared__ float s_cnt[N_BINS];
    __shared__ float s_conf[N_BINS];
    __shared__ float s_acc[N_BINS];
    __shared__ bool  s_last;

    int tid = threadIdx.x;
    if (tid < N_BINS) {
        s_cnt[tid]  = 0.0f;
        s_conf[tid] = 0.0f;
        s_acc[tid]  = 0.0f;
    }
    __syncthreads();

    int lane   = tid & 31;
    int seg    = lane >> 2;                // row within group (0..7)
    int sub    = lane & 3;                 // lane within row segment
    int warp   = (blockIdx.x * blockDim.x + tid) >> 5;
    int nwarps = (gridDim.x * blockDim.x) >> 5;

    float r_cnt = 0.0f, r_conf = 0.0f, r_acc = 0.0f;

    for (int base = warp * RPW; base < nrows; base += nwarps * RPW) {
        int row  = base + seg;
        int rowc = (row < nrows) ? row : (nrows - 1);   // clamp tail

        // label for my segment's row (8 consecutive ints, broadcast in segment)
        int lab = labels[rowc];

        // front-batched row loads: 8 LDG.128 per lane, warp covers 4 KB
        float4 v[RPW];
        const float4* rp = logits4 + (size_t)rowc * 32 + sub;
        #pragma unroll
        for (int i = 0; i < RPW; i++) v[i] = rp[4 * i];

        // label's logit (hits the L1 lines the row loads fetch; MSHR-merged)
        float lv = logits[(size_t)rowc * 128 + lab];

        // ---- per-lane max over 32 values, tree ----
        float pm[RPW];
        #pragma unroll
        for (int i = 0; i < RPW; i++)
            pm[i] = fmaxf(fmaxf(v[i].x, v[i].y), fmaxf(v[i].z, v[i].w));
        float m = fmaxf(fmaxf(fmaxf(pm[0], pm[1]), fmaxf(pm[2], pm[3])),
                        fmaxf(fmaxf(pm[4], pm[5]), fmaxf(pm[6], pm[7])));
        // segment butterfly: 2 levels, all 8 rows reduced per instruction
        m = fmaxf(m, __shfl_xor_sync(0xffffffffu, m, 1));
        m = fmaxf(m, __shfl_xor_sync(0xffffffffu, m, 2));

        // ---- sum of exp(x - m) = ex2(x*log2e - m*log2e) ----
        float mL = m * LOG2E;
        float ps[RPW];
        #pragma unroll
        for (int i = 0; i < RPW; i++) {
            float e0 = ex2f(fmaf(v[i].x, LOG2E, -mL));
            float e1 = ex2f(fmaf(v[i].y, LOG2E, -mL));
            float e2 = ex2f(fmaf(v[i].z, LOG2E, -mL));
            float e3 = ex2f(fmaf(v[i].w, LOG2E, -mL));
            ps[i] = (e0 + e1) + (e2 + e3);
        }
        float s = ((ps[0] + ps[1]) + (ps[2] + ps[3]))
                + ((ps[4] + ps[5]) + (ps[6] + ps[7]));
        s += __shfl_xor_sync(0xffffffffu, s, 1);
        s += __shfl_xor_sync(0xffffffffu, s, 2);

        float conf = __fdividef(1.0f, s);      // = exp(max)/sum exp

        // one ballot covers all 8 rows' accuracy checks (ties: measure zero)
        unsigned b = __ballot_sync(0xffffffffu, lv == m);

        int nr = min(RPW, nrows - base);
        #pragma unroll
        for (int r = 0; r < RPW; r++) {
            float cf = __shfl_sync(0xffffffffu, conf, r * 4);
            // bin i covers (i/15, (i+1)/15]; conf >= 1/128 -> bin >= 0 always
            int bin = min(__float2int_ru(cf * (float)N_BINS) - 1, N_BINS - 1);
            if (bin == lane && r < nr) {
                r_cnt  += 1.0f;
                r_conf += cf;
                r_acc  += (float)((b >> (4 * r)) & 1u);
            }
        }
    }

    // ---- flush: registers -> shared -> global (once per block) ----
    if (lane < N_BINS && r_cnt != 0.0f) {
        atomicAdd(&s_cnt[lane],  r_cnt);
        atomicAdd(&s_conf[lane], r_conf);
        atomicAdd(&s_acc[lane],  r_acc);
    }
    __syncthreads();
    if (tid < N_BINS) {
        float c = s_cnt[tid];
        if (c != 0.0f) {
            atomicAdd(&g_cnt[tid],  c);
            atomicAdd(&g_conf[tid], s_conf[tid]);
            atomicAdd(&g_acc[tid],  s_acc[tid]);
        }
    }
    __threadfence();
    __syncthreads();

    // ---- last block finalizes (fused; no second launch) ----
    if (tid == 0)
        s_last = (atomicAdd(&g_done, 1u) == gridDim.x - 1u);
    __syncthreads();
    if (s_last && tid == 0) {
        volatile float* vc = g_cnt;
        volatile float* vp = g_conf;
        volatile float* va = g_acc;
        float mce = -CUDART_INF_F;
        #pragma unroll
        for (int i = 0; i < N_BINS; i++) {
            float c    = vc[i];
            float prob = 0.0f, accu = 0.0f;
            if (c > 0.0f) {
                prob = vp[i] / c;
                accu = va[i] / c;
                float gap = fabsf(prob - accu);
                if (gap > mce) mce = gap;
            }
            out[1 + i]          = prob;
            out[1 + N_BINS + i] = accu;
            vc[i] = 0.0f; vp[i] = 0.0f; va[i] = 0.0f;   // reset for next replay
        }
        out[0] = mce;
        g_done = 0u;
    }
}

extern "C" void kernel_launch(void* const* d_in, const int* in_sizes, int n_in,
                              void* d_out, int out_size) {
    const float4* logits4 = (const float4*)d_in[0];
    const float*  logits  = (const float*)d_in[0];
    const int*    labels  = (const int*)d_in[1];
    int nrows = in_sizes[1];               // labels element count == N rows

    // ~3 CTAs/SM resident; grid-stride handles any occupancy outcome
    mce_main_kernel<<<444, 256>>>(logits4, logits, labels, (float*)d_out, nrows);
}